// round 1
// baseline (speedup 1.0000x reference)
#include <cuda_runtime.h>

#define MP1 524288
#define NXP 32768
#define PP  128
#define HT  128
#define HE  64

// scratch (no cudaMalloc allowed)
__device__ float g_b[PP];
__device__ float g_c[PP + 1];   // c[0..127], d0 at [128]

// ---------------------------------------------------------------- branch
__global__ __launch_bounds__(1024) void k_branch(const float* __restrict__ Wb,
                                                 const float* __restrict__ a,
                                                 const float* __restrict__ bb) {
    int p = blockIdx.x;
    const float4* row = reinterpret_cast<const float4*>(Wb + (size_t)p * MP1);
    const float4* a4  = reinterpret_cast<const float4*>(a);
    float s = 0.f;
#pragma unroll 4
    for (int i = threadIdx.x; i < MP1 / 4; i += 1024) {
        float4 w = row[i], v = a4[i];
        s += w.x * v.x + w.y * v.y + w.z * v.z + w.w * v.w;
    }
    __shared__ float red[32];
    for (int o = 16; o; o >>= 1) s += __shfl_down_sync(0xffffffffu, s, o);
    if ((threadIdx.x & 31) == 0) red[threadIdx.x >> 5] = s;
    __syncthreads();
    if (threadIdx.x < 32) {
        float v = red[threadIdx.x];
        for (int o = 16; o; o >>= 1) v += __shfl_down_sync(0xffffffffu, v, o);
        if (threadIdx.x == 0) g_b[p] = v + bb[p];
    }
}

// ------------------------------------------------- c = Wt3^T b, d0 = b.bt3
__global__ void k_coeff(const float* __restrict__ Wt3, const float* __restrict__ bt3) {
    __shared__ float sb[PP];
    __shared__ float w4[4];
    int k = threadIdx.x;
    sb[k] = g_b[k];
    __syncthreads();
    float s = 0.f;
#pragma unroll 8
    for (int p = 0; p < PP; ++p) s += sb[p] * Wt3[p * PP + k];
    g_c[k] = s;
    float v = sb[k] * bt3[k];
    for (int o = 16; o; o >>= 1) v += __shfl_down_sync(0xffffffffu, v, o);
    if ((k & 31) == 0) w4[k >> 5] = v;
    __syncthreads();
    if (k == 0) g_c[PP] = w4[0] + w4[1] + w4[2] + w4[3];
}

// ---------------------------------------------------------------- main
// smem layout (floats)
#define WPAD 132
#define EPAD 68
#define OFF_WT2 0                    // 128*132 = 16896
#define OFF_WE2 16896                // 64*68   = 4352
#define OFF_C   21248
#define OFF_W0  21376
#define OFF_ZC  21504
#define OFF_BT2 21632
#define OFF_P   21760
#define OFF_Q   21824
#define OFF_BE1 21888
#define OFF_BE2 21952
#define OFF_W3  22016
#define OFF_D0  22080
#define OFF_LANE 22084
// per-lane region
#define L_H1 0        // 128 * 4 (float4 jets per unit)
#define L_E1 512      // 64 * 12 (9 comps padded to 12)
#define L_EP 1280     // 2 * 64 * 12
#define L_U  2816     // 4 (+pad)
#define L_FP 2824     // 2 warps * 8
#define LANE_SZ 2840
#define NLANE 2
#define TPB 256
#define GRID 296
#define STRIDE (GRID * NLANE)                 // 592
#define ITERS ((NXP + STRIDE - 1) / STRIDE)   // 56
#define SMEM_FLOATS (OFF_LANE + NLANE * LANE_SZ)

__global__ __launch_bounds__(TPB, 2) void k_main(
    const float* __restrict__ x, const float* __restrict__ tptr,
    const float* __restrict__ Wt1, const float* __restrict__ bt1,
    const float* __restrict__ Wt2, const float* __restrict__ bt2,
    const float* __restrict__ We1, const float* __restrict__ be1,
    const float* __restrict__ We2, const float* __restrict__ be2,
    const float* __restrict__ We3, float* __restrict__ out)
{
    extern __shared__ float sm[];
    const int tid = threadIdx.x;

    // ---- stage all weights into smem (padded rows for conflict-free f4 loads)
    {
        const float4* src = reinterpret_cast<const float4*>(Wt2);
#pragma unroll
        for (int i = tid; i < HT * HT / 4; i += TPB) {
            int e = i * 4, j = e >> 7, k = e & 127;
            *reinterpret_cast<float4*>(&sm[OFF_WT2 + j * WPAD + k]) = src[i];
        }
        const float4* se = reinterpret_cast<const float4*>(We2);
#pragma unroll
        for (int i = tid; i < HE * HE / 4; i += TPB) {
            int e = i * 4, j = e >> 6, k = e & 63;
            *reinterpret_cast<float4*>(&sm[OFF_WE2 + j * EPAD + k]) = se[i];
        }
        float tv = *tptr;
        if (tid < 128) {
            sm[OFF_C + tid]   = g_c[tid];
            float w0 = Wt1[2 * tid];
            sm[OFF_W0 + tid]  = w0;
            sm[OFF_ZC + tid]  = Wt1[2 * tid + 1] * tv + bt1[tid];
            sm[OFF_BT2 + tid] = bt2[tid];
        }
        if (tid < 64) {
            sm[OFF_P + tid]   = We1[2 * tid];
            sm[OFF_Q + tid]   = We1[2 * tid + 1];
            sm[OFF_BE1 + tid] = be1[tid];
            sm[OFF_BE2 + tid] = be2[tid];
            sm[OFF_W3 + tid]  = We3[tid];
        }
        if (tid == 0) sm[OFF_D0] = g_c[PP];
    }
    __syncthreads();

    const int lane = tid >> 7;          // point-lane within block
    const int j    = tid & 127;         // unit index within lane
    float* L = sm + OFF_LANE + lane * LANE_SZ;
    const int wl  = j & 31;
    const int wrp = j >> 5;
    const int lane_gid = blockIdx.x * NLANE + lane;

    for (int it = 0; it < ITERS; ++it) {
        const int pt = lane_gid + it * STRIDE;
        const bool active = pt < NXP;

        // ---- phase 1: trunk layer-1 jets (1-var, only z1' nonzero)
        {
            float xi = active ? x[pt] : 0.f;
            float w0 = sm[OFF_W0 + j];
            float T  = tanhf(w0 * xi + sm[OFF_ZC + j]);
            float s  = 1.f - T * T;
            float d2 = -2.f * T * s;
            float d3 = -2.f * s * (1.f - 3.f * T * T);
            float w2 = w0 * w0;
            *reinterpret_cast<float4*>(&L[L_H1 + j * 4]) =
                make_float4(T, s * w0, d2 * w2, d3 * w2 * w0);
        }
        __syncthreads();

        // ---- phase 2: trunk layer-2 GEMV (4 streams) + tanh jet + c-dot
        {
            float acc0 = sm[OFF_BT2 + j], acc1 = 0.f, acc2 = 0.f, acc3 = 0.f;
            const float4* wrow = reinterpret_cast<const float4*>(&sm[OFF_WT2 + j * WPAD]);
            const float4* hj   = reinterpret_cast<const float4*>(&L[L_H1]);
#pragma unroll
            for (int k4 = 0; k4 < 32; ++k4) {
                float4 w  = wrow[k4];
                float4 hA = hj[4 * k4 + 0], hB = hj[4 * k4 + 1];
                float4 hC = hj[4 * k4 + 2], hD = hj[4 * k4 + 3];
                acc0 += w.x * hA.x; acc1 += w.x * hA.y; acc2 += w.x * hA.z; acc3 += w.x * hA.w;
                acc0 += w.y * hB.x; acc1 += w.y * hB.y; acc2 += w.y * hB.z; acc3 += w.y * hB.w;
                acc0 += w.z * hC.x; acc1 += w.z * hC.y; acc2 += w.z * hC.z; acc3 += w.z * hC.w;
                acc0 += w.w * hD.x; acc1 += w.w * hD.y; acc2 += w.w * hD.z; acc3 += w.w * hD.w;
            }
            float T  = tanhf(acc0);
            float s  = 1.f - T * T;
            float d2 = -2.f * T * s;
            float d3 = -2.f * s * (1.f - 3.f * T * T);
            float g1 = s * acc1;
            float g2 = s * acc2 + d2 * acc1 * acc1;
            float g3 = s * acc3 + 3.f * d2 * acc1 * acc2 + d3 * acc1 * acc1 * acc1;
            float cc = sm[OFF_C + j];
            __syncthreads();   // everyone finished reading L_H1
            *reinterpret_cast<float4*>(&L[L_H1 + j * 4]) =
                make_float4(cc * T, cc * g1, cc * g2, cc * g3);
        }
        __syncthreads();
        {   // per-stream reduction: warp wrp reduces stream wrp
            float v = L[L_H1 + wl * 4 + wrp] + L[L_H1 + (wl + 32) * 4 + wrp]
                    + L[L_H1 + (wl + 64) * 4 + wrp] + L[L_H1 + (wl + 96) * 4 + wrp];
            for (int o = 16; o; o >>= 1) v += __shfl_down_sync(0xffffffffu, v, o);
            if (wl == 0) {
                if (wrp == 0) v += sm[OFF_D0];
                L[L_U + wrp] = v;
            }
        }
        __syncthreads();

        // ---- phase 3: EnergyNet layer-1 2-var jets (seeds y=u, z=u_x)
        if (j < 64) {
            float y = L[L_U + 0], z = L[L_U + 1];
            float p = sm[OFF_P + j], q = sm[OFF_Q + j];
            float T  = tanhf(p * y + q * z + sm[OFF_BE1 + j]);
            float s  = 1.f - T * T;
            float d2 = -2.f * T * s;
            float d3 = -2.f * s * (1.f - 3.f * T * T);
            float* e = &L[L_E1 + j * 12];
            *reinterpret_cast<float4*>(e)     = make_float4(T, s * p, s * q, d2 * p * p);
            *reinterpret_cast<float4*>(e + 4) = make_float4(d2 * p * q, d2 * q * q,
                                                            d3 * p * p * q, d3 * p * q * q);
            e[8] = d3 * q * q * q;
        }
        __syncthreads();

        // ---- phase 4: EnergyNet layer-2 GEMV, 9 streams, k-split over halves
        {
            const int j2 = j & 63, half = j >> 6;
            float a0=0,a1=0,a2=0,a3=0,a4=0,a5=0,a6=0,a7=0,a8=0;
            const float4* wrow =
                reinterpret_cast<const float4*>(&sm[OFF_WE2 + j2 * EPAD + half * 32]);
            const float* eb = &L[L_E1 + half * 32 * 12];
#pragma unroll
            for (int k4 = 0; k4 < 8; ++k4) {
                float4 w = wrow[k4];
#pragma unroll
                for (int ss = 0; ss < 4; ++ss) {
                    const float* e = eb + (4 * k4 + ss) * 12;
                    float wk = (ss == 0) ? w.x : (ss == 1) ? w.y : (ss == 2) ? w.z : w.w;
                    float4 eA = *reinterpret_cast<const float4*>(e);
                    float4 eB = *reinterpret_cast<const float4*>(e + 4);
                    float  eC = e[8];
                    a0 += wk * eA.x; a1 += wk * eA.y; a2 += wk * eA.z; a3 += wk * eA.w;
                    a4 += wk * eB.x; a5 += wk * eB.y; a6 += wk * eB.z; a7 += wk * eB.w;
                    a8 += wk * eC;
                }
            }
            float* dst = &L[L_EP + (half * 64 + j2) * 12];
            *reinterpret_cast<float4*>(dst)     = make_float4(a0, a1, a2, a3);
            *reinterpret_cast<float4*>(dst + 4) = make_float4(a4, a5, a6, a7);
            dst[8] = a8;
        }
        __syncthreads();

        // ---- phase 5: combine halves, multivariate tanh jet, We3 reduction
        if (j < 64) {
            const float* p0 = &L[L_EP + j * 12];
            const float* p1 = &L[L_EP + (64 + j) * 12];
            float a0   = p0[0] + p1[0] + sm[OFF_BE2 + j];
            float ay   = p0[1] + p1[1], az   = p0[2] + p1[2];
            float ayy  = p0[3] + p1[3], ayz  = p0[4] + p1[4], azz = p0[5] + p1[5];
            float ayyz = p0[6] + p1[6], ayzz = p0[7] + p1[7], azzz = p0[8] + p1[8];
            float T  = tanhf(a0);
            float s  = 1.f - T * T;
            float d2 = -2.f * T * s;
            float d3 = -2.f * s * (1.f - 3.f * T * T);
            float vyy  = s * ayy  + d2 * ay * ay;
            float vzz  = s * azz  + d2 * az * az;
            float vyyz = s * ayyz + d2 * (ayy * az + 2.f * ayz * ay) + d3 * ay * ay * az;
            float vyzz = s * ayzz + d2 * (azz * ay + 2.f * ayz * az) + d3 * ay * az * az;
            float vzzz = s * azzz + 3.f * d2 * azz * az + d3 * az * az * az;
            float w3 = sm[OFF_W3 + j];
            float r0 = w3 * vyy, r1 = w3 * vzz, r2 = w3 * vyyz, r3 = w3 * vyzz, r4 = w3 * vzzz;
            for (int o = 16; o; o >>= 1) {
                r0 += __shfl_down_sync(0xffffffffu, r0, o);
                r1 += __shfl_down_sync(0xffffffffu, r1, o);
                r2 += __shfl_down_sync(0xffffffffu, r2, o);
                r3 += __shfl_down_sync(0xffffffffu, r3, o);
                r4 += __shfl_down_sync(0xffffffffu, r4, o);
            }
            if (wl == 0) {
                float* fp = &L[L_FP + wrp * 8];
                fp[0] = r0; fp[1] = r1; fp[2] = r2; fp[3] = r3; fp[4] = r4;
            }
        }
        __syncthreads();
        if (j == 0 && active) {
            float Fyy  = L[L_FP + 0] + L[L_FP + 8];
            float Fzz  = L[L_FP + 1] + L[L_FP + 9];
            float Fyyz = L[L_FP + 2] + L[L_FP + 10];
            float Fyzz = L[L_FP + 3] + L[L_FP + 11];
            float Fzzz = L[L_FP + 4] + L[L_FP + 12];
            float u1 = L[L_U + 1], u2 = L[L_U + 2], u3 = L[L_U + 3];
            // -F_yx + F_zxx with exact F_yz cancellation
            out[pt] = -Fyy * u1 + Fzz * u3 + Fyyz * u1 * u1
                    + 2.f * Fyzz * u1 * u2 + Fzzz * u2 * u2;
        }
        // next iteration's L_H1 writers are safe: last L_H1 readers synced above
    }
}

// ---------------------------------------------------------------- launch
extern "C" void kernel_launch(void* const* d_in, const int* in_sizes, int n_in,
                              void* d_out, int out_size) {
    const float* a   = (const float*)d_in[0];
    const float* x   = (const float*)d_in[1];
    const float* t   = (const float*)d_in[2];
    const float* Wb  = (const float*)d_in[3];
    const float* bb  = (const float*)d_in[4];
    const float* Wt1 = (const float*)d_in[5];
    const float* bt1 = (const float*)d_in[6];
    const float* Wt2 = (const float*)d_in[7];
    const float* bt2 = (const float*)d_in[8];
    const float* Wt3 = (const float*)d_in[9];
    const float* bt3 = (const float*)d_in[10];
    const float* We1 = (const float*)d_in[11];
    const float* be1 = (const float*)d_in[12];
    const float* We2 = (const float*)d_in[13];
    const float* be2 = (const float*)d_in[14];
    const float* We3 = (const float*)d_in[15];
    (void)in_sizes; (void)n_in;
    float* out = (float*)d_out; (void)out_size;

    k_branch<<<PP, 1024>>>(Wb, a, bb);
    k_coeff<<<1, 128>>>(Wt3, bt3);

    size_t smem = SMEM_FLOATS * sizeof(float);
    cudaFuncSetAttribute(k_main, cudaFuncAttributeMaxDynamicSharedMemorySize, (int)smem);
    k_main<<<GRID, TPB, smem>>>(x, t, Wt1, bt1, Wt2, bt2,
                                We1, be1, We2, be2, We3, out);
}